// round 6
// baseline (speedup 1.0000x reference)
#include <cuda_runtime.h>
#include <math.h>

typedef unsigned long long ull;

#define Mdim 2048
#define Ndim 256
#define Kdim 256
#define ITERS 1000
#define NS_ITERS 10
#define JREG 44            // j per quarter in registers
#define JSMEM 20           // j per quarter from SMEM (44+20=64)

// packed dual-fp32 FMA; ptxas never auto-fuses this from C++
#define FMA2(d, a, b, c) \
    asm("fma.rn.f32x2 %0, %1, %2, %3;" : "=l"(d) : "l"(a), "l"(b), "l"(c))
#define ADD2(d, a, b) \
    asm("add.rn.f32x2 %0, %1, %2;" : "=l"(d) : "l"(a), "l"(b))

__device__ __forceinline__ void unpack2(float& lo, float& hi, ull v) {
    asm("mov.b64 {%0, %1}, %2;" : "=f"(lo), "=f"(hi) : "l"(v));
}
__device__ __forceinline__ ull shfl_xor_u64(ull v, int m) {
    unsigned lo = (unsigned)v, hi = (unsigned)(v >> 32);
    lo = __shfl_xor_sync(0xffffffffu, lo, m);
    hi = __shfl_xor_sync(0xffffffffu, hi, m);
    return ((ull)hi << 32) | lo;
}

// Scratch (allocation-free rule: __device__ globals)
__device__ float g_G[Ndim * Ndim];
__device__ float g_Atb[Ndim * Kdim];
__device__ float g_X0[Ndim * Ndim];
__device__ float g_X1[Ndim * Ndim];
__device__ float g_Y[Ndim * Ndim];
__device__ float g_a[1];

// ---------------------------------------------------------------------------
// C = A^T X  (A: [M,N], X: [M,K], C: [N,K]), optionally += rho*I on diagonal
// ---------------------------------------------------------------------------
__global__ void atx_kernel(const float* __restrict__ A, const float* __restrict__ X,
                           float* __restrict__ C, const float* __restrict__ rho_p,
                           int addDiag)
{
    __shared__ float As[32][33];
    __shared__ float Xs[32][33];
    const int tx = threadIdx.x, ty = threadIdx.y;
    const int i0 = blockIdx.x * 32, j0 = blockIdx.y * 32;
    float acc = 0.f;
    for (int mt = 0; mt < Mdim; mt += 32) {
        As[ty][tx] = A[(mt + ty) * Ndim + i0 + tx];
        Xs[ty][tx] = X[(mt + ty) * Kdim + j0 + tx];
        __syncthreads();
#pragma unroll
        for (int mm = 0; mm < 32; mm++)
            acc = fmaf(As[mm][ty], Xs[mm][tx], acc);
        __syncthreads();
    }
    const int i = i0 + ty, j = j0 + tx;
    if (addDiag && i == j) acc += fabsf(rho_p[0]) + 1e-10f;
    C[i * Kdim + j] = acc;
}

// a = 1/||G||_inf  (G symmetric)
__global__ void norm_kernel(const float* __restrict__ G, float* __restrict__ a_out)
{
    __shared__ float red[256];
    const int t = threadIdx.x;
    float s = 0.f;
    for (int j = 0; j < Ndim; j++) s += fabsf(G[j * Ndim + t]);
    red[t] = s;
    __syncthreads();
    for (int off = 128; off > 0; off >>= 1) {
        if (t < off) red[t] = fmaxf(red[t], red[t + off]);
        __syncthreads();
    }
    if (t == 0) a_out[0] = 1.0f / red[0];
}

__global__ void init_x_kernel(float* __restrict__ X, const float* __restrict__ a_p)
{
    const int idx = blockIdx.x * blockDim.x + threadIdx.x;
    const int i = idx >> 8, j = idx & 255;
    X[idx] = (i == j) ? a_p[0] : 0.f;
}

// 256^3 GEMM: mode 0: C = A@B ;  mode 1: C = 2A - A@B  (Newton-Schulz)
__global__ void gemm256_kernel(const float* __restrict__ A, const float* __restrict__ B,
                               float* __restrict__ C, int ns_mode)
{
    __shared__ float As[32][33];
    __shared__ float Bs[32][33];
    const int tx = threadIdx.x, ty = threadIdx.y;
    const int i = blockIdx.y * 32 + ty, j = blockIdx.x * 32 + tx;
    float acc = 0.f;
    for (int kt = 0; kt < Ndim; kt += 32) {
        As[ty][tx] = A[i * Ndim + kt + tx];
        Bs[ty][tx] = B[(kt + ty) * Ndim + j];
        __syncthreads();
#pragma unroll
        for (int mm = 0; mm < 32; mm++)
            acc = fmaf(As[ty][mm], Bs[mm][tx], acc);
        __syncthreads();
    }
    C[i * Ndim + j] = ns_mode ? fmaf(2.f, A[i * Ndim + j], -acc) : acc;
}

// ---------------------------------------------------------------------------
// Persistent ADMM v4: 128 blocks x 2 cols, 256 threads, 8 warps.
// Warp w owns rows [32w, 32w+32). lane = 8q + rp: thread covers rows
// r0=32w+4rp..+3, j-quarter [64q,64q+64): k<JREG from registers, rest SMEM.
// Cross-q reduction via 2x shfl.bfly (xor 8,16) — bit-identical in all
// lanes, so z/u state and the update are computed redundantly per q with no
// SMEM partials. ONE barrier per iteration (w double-buffered).
// Uses Minv symmetry: Tpred[r] = sum_j Minv[j][r] * w[j].
// ---------------------------------------------------------------------------
__global__ void __launch_bounds__(256, 1) admm_kernel(
    const float* __restrict__ Minv, const float* __restrict__ Atb,
    const float* __restrict__ rho_p, const float* __restrict__ lam_p,
    float* __restrict__ out)
{
    extern __shared__ float sm[];
    float*  MinvS = sm;                                // 4*JSMEM rows x 256
    float4* wbuf  = (float4*)(sm + 4 * JSMEM * Ndim);  // [2][256] splat quads

    const int tid  = threadIdx.x;
    const int wid  = tid >> 5;
    const int lane = tid & 31;
    const int q    = lane >> 3;
    const int rp   = lane & 7;
    const int r0   = 32 * wid + 4 * rp;
    const int c0   = blockIdx.x * 2;

    const float rho = fabsf(rho_p[0]) + 1e-10f;
    const float tau = fabsf(lam_p[0]) / rho;

    // Stage compact SMEM rows: global j = 64*(cr/JSMEM) + JREG + cr%JSMEM
    {
        const float4* src = (const float4*)Minv;
        float4* dst = (float4*)MinvS;
        for (int idx = tid; idx < 4 * JSMEM * 64; idx += 256) {
            const int cr = idx >> 6, within = idx & 63;
            const int j = 64 * (cr / JSMEM) + JREG + (cr % JSMEM);
            dst[idx] = src[j * 64 + within];
        }
    }

    // Register Minv: j = 64q + k, k < JREG; ull pairs (r0,r1),(r2,r3)
    ull mreg[2 * JREG];
#pragma unroll
    for (int k = 0; k < JREG; k++) {
        const ulonglong2 v =
            __ldg((const ulonglong2*)(Minv + (64 * q + k) * Ndim + r0));
        mreg[2 * k]     = v.x;
        mreg[2 * k + 1] = v.y;
    }

    // Per-thread state for rows r0..r0+3, cols c0,c0+1 (redundant across q)
    float atb[8], u[8], tp[8];
#pragma unroll
    for (int r = 0; r < 4; r++) {
        atb[2 * r]     = __ldg(Atb + (r0 + r) * Kdim + c0);
        atb[2 * r + 1] = __ldg(Atb + (r0 + r) * Kdim + c0 + 1);
        u[2 * r] = 0.f; u[2 * r + 1] = 0.f;
        tp[2 * r] = 0.f; tp[2 * r + 1] = 0.f;
    }
    // init w = Atb (z=u=0), splat-stored; row tid written by thread tid
    {
        const float a0 = __ldg(Atb + tid * Kdim + c0);
        const float a1 = __ldg(Atb + tid * Kdim + c0 + 1);
        wbuf[tid] = make_float4(a0, a0, a1, a1);
    }
    __syncthreads();

    const float* MsBase = MinvS + (JSMEM * q) * Ndim + r0;

    int b = 0;
    for (int it = 0; it < ITERS; ++it) {
        const ulonglong2* __restrict__ wb =
            (const ulonglong2*)(wbuf + b * 256) + 64 * q;

        ull a00 = 0ull, a10 = 0ull, a01 = 0ull, a11 = 0ull;
#pragma unroll
        for (int k = 0; k < JREG; k++) {
            const ulonglong2 wv = wb[k];               // (w0,w0),(w1,w1)
            FMA2(a00, mreg[2 * k],     wv.x, a00);
            FMA2(a10, mreg[2 * k + 1], wv.x, a10);
            FMA2(a01, mreg[2 * k],     wv.y, a01);
            FMA2(a11, mreg[2 * k + 1], wv.y, a11);
        }
#pragma unroll
        for (int k = 0; k < JSMEM; k++) {
            const ulonglong2 m = *(const ulonglong2*)(MsBase + k * Ndim);
            const ulonglong2 wv = wb[JREG + k];
            FMA2(a00, m.x, wv.x, a00);
            FMA2(a10, m.y, wv.x, a10);
            FMA2(a01, m.x, wv.y, a01);
            FMA2(a11, m.y, wv.y, a11);
        }

        // cross-q reduce: bfly xor 8, xor 16 (bit-identical in all lanes)
        ull t0;
        t0 = shfl_xor_u64(a00,  8); ADD2(a00, a00, t0);
        t0 = shfl_xor_u64(a00, 16); ADD2(a00, a00, t0);
        t0 = shfl_xor_u64(a10,  8); ADD2(a10, a10, t0);
        t0 = shfl_xor_u64(a10, 16); ADD2(a10, a10, t0);
        t0 = shfl_xor_u64(a01,  8); ADD2(a01, a01, t0);
        t0 = shfl_xor_u64(a01, 16); ADD2(a01, a01, t0);
        t0 = shfl_xor_u64(a11,  8); ADD2(a11, a11, t0);
        t0 = shfl_xor_u64(a11, 16); ADD2(a11, a11, t0);

        // unpack: rows (r0,r1) in a00/a01, rows (r2,r3) in a10/a11
        unpack2(tp[0], tp[2], a00);   // col0: r0, r1
        unpack2(tp[4], tp[6], a10);   // col0: r2, r3
        unpack2(tp[1], tp[3], a01);   // col1: r0, r1
        unpack2(tp[5], tp[7], a11);   // col1: r2, r3

        // update (redundant across q, consistent), q==0 stores w
        float w2[8];
#pragma unroll
        for (int i = 0; i < 8; i++) {
            const float g  = tp[i] + u[i];
            float zn = fmaxf(g - tau, 0.f) + fminf(g + tau, 0.f);
            zn = fminf(fmaxf(zn, 0.f), 1.f);
            u[i] += tp[i] - zn;
            w2[i] = fmaf(rho, zn - u[i], atb[i]);
        }
        if (q == 0) {
            float4* wd = wbuf + (b ^ 1) * 256 + r0;
#pragma unroll
            for (int r = 0; r < 4; r++)
                wd[r] = make_float4(w2[2 * r], w2[2 * r],
                                    w2[2 * r + 1], w2[2 * r + 1]);
        }
        __syncthreads();
        b ^= 1;
    }

    if (q == 0) {
#pragma unroll
        for (int r = 0; r < 4; r++)
            *(float2*)(out + (r0 + r) * Kdim + c0) =
                make_float2(tp[2 * r], tp[2 * r + 1]);
    }
}

// ---------------------------------------------------------------------------
extern "C" void kernel_launch(void* const* d_in, const int* in_sizes, int n_in,
                              void* d_out, int out_size)
{
    // metadata order: T, s_A, s_mic_data, rho_param, lam_param
    const float* s_A   = (const float*)d_in[1];
    const float* s_mic = (const float*)d_in[2];
    const float* rho_p = (const float*)d_in[3];
    const float* lam_p = (const float*)d_in[4];
    float* out = (float*)d_out;

    float *G, *Atb, *X0, *X1, *Y, *ap;
    cudaGetSymbolAddress((void**)&G,   g_G);
    cudaGetSymbolAddress((void**)&Atb, g_Atb);
    cudaGetSymbolAddress((void**)&X0,  g_X0);
    cudaGetSymbolAddress((void**)&X1,  g_X1);
    cudaGetSymbolAddress((void**)&Y,   g_Y);
    cudaGetSymbolAddress((void**)&ap,  g_a);

    const size_t shmem = (size_t)(4 * JSMEM * Ndim) * sizeof(float)
                       + 2 * 256 * sizeof(float4);
    cudaFuncSetAttribute(admm_kernel, cudaFuncAttributeMaxDynamicSharedMemorySize,
                         (int)shmem);

    dim3 tb(32, 32);
    dim3 gb(8, 8);
    atx_kernel<<<gb, tb>>>(s_A, s_A,   G,   rho_p, 1);
    atx_kernel<<<gb, tb>>>(s_A, s_mic, Atb, rho_p, 0);

    // Newton-Schulz inverse: X0 = I/||G||inf; X <- 2X - X@(G@X)
    norm_kernel<<<1, 256>>>(G, ap);
    init_x_kernel<<<256, 256>>>(X0, ap);
    float* Xc = X0; float* Xn = X1;
    for (int i = 0; i < NS_ITERS; i++) {
        gemm256_kernel<<<gb, tb>>>(G,  Xc, Y,  0);  // Y  = G@X
        gemm256_kernel<<<gb, tb>>>(Xc, Y,  Xn, 1);  // Xn = 2X - X@Y
        float* t = Xc; Xc = Xn; Xn = t;
    }
    // NS_ITERS even -> result back in X0 (== Xc)

    admm_kernel<<<128, 256, shmem>>>(Xc, Atb, rho_p, lam_p, out);
}

// round 8
// speedup vs baseline: 1.3448x; 1.3448x over previous
#include <cuda_runtime.h>
#include <math.h>

typedef unsigned long long ull;

#define Mdim 2048
#define Ndim 256
#define Kdim 256
#define ITERS 1000
#define NS_ITERS 8
#define JREG 44            // j per quarter in registers
#define JSMEM 20           // j per quarter from SMEM (44+20=64)
#define WSTRIDE 260        // 256 w slots + 4 pad float4s (1 per 64) per buffer

// packed dual-fp32 FMA; ptxas never auto-fuses this from C++
#define FMA2(d, a, b, c) \
    asm("fma.rn.f32x2 %0, %1, %2, %3;" : "=l"(d) : "l"(a), "l"(b), "l"(c))
#define ADD2(d, a, b) \
    asm("add.rn.f32x2 %0, %1, %2;" : "=l"(d) : "l"(a), "l"(b))

__device__ __forceinline__ void unpack2(float& lo, float& hi, ull v) {
    asm("mov.b64 {%0, %1}, %2;" : "=f"(lo), "=f"(hi) : "l"(v));
}
__device__ __forceinline__ ull shfl_xor_u64(ull v, int m) {
    unsigned lo = (unsigned)v, hi = (unsigned)(v >> 32);
    lo = __shfl_xor_sync(0xffffffffu, lo, m);
    hi = __shfl_xor_sync(0xffffffffu, hi, m);
    return ((ull)hi << 32) | lo;
}

// Scratch (allocation-free rule: __device__ globals)
__device__ float g_G[Ndim * Ndim];
__device__ float g_Atb[Ndim * Kdim];
__device__ float g_X0[Ndim * Ndim];
__device__ float g_X1[Ndim * Ndim];
__device__ float g_Y[Ndim * Ndim];
__device__ float g_a[1];

// ---------------------------------------------------------------------------
// C += (A^T X) over M-chunk blockIdx.z (A: [M,N], X: [M,K]); atomic combine.
// z==0 also adds rho to the diagonal. C must be zeroed before launch.
// ---------------------------------------------------------------------------
__global__ void atx_kernel(const float* __restrict__ A, const float* __restrict__ X,
                           float* __restrict__ C, const float* __restrict__ rho_p,
                           int addDiag)
{
    __shared__ float As[32][33];
    __shared__ float Xs[32][33];
    const int tx = threadIdx.x, ty = threadIdx.y;
    const int i0 = blockIdx.x * 32, j0 = blockIdx.y * 32;
    const int m0 = blockIdx.z * (Mdim / 4);
    float acc = 0.f;
    for (int mt = m0; mt < m0 + Mdim / 4; mt += 32) {
        As[ty][tx] = A[(mt + ty) * Ndim + i0 + tx];
        Xs[ty][tx] = X[(mt + ty) * Kdim + j0 + tx];
        __syncthreads();
#pragma unroll
        for (int mm = 0; mm < 32; mm++)
            acc = fmaf(As[mm][ty], Xs[mm][tx], acc);
        __syncthreads();
    }
    const int i = i0 + ty, j = j0 + tx;
    if (addDiag && i == j && blockIdx.z == 0) acc += fabsf(rho_p[0]) + 1e-10f;
    atomicAdd(&C[i * Kdim + j], acc);
}

// a = 1/||G||_inf  (G symmetric)
__global__ void norm_kernel(const float* __restrict__ G, float* __restrict__ a_out)
{
    __shared__ float red[256];
    const int t = threadIdx.x;
    float s = 0.f;
    for (int j = 0; j < Ndim; j++) s += fabsf(G[j * Ndim + t]);
    red[t] = s;
    __syncthreads();
    for (int off = 128; off > 0; off >>= 1) {
        if (t < off) red[t] = fmaxf(red[t], red[t + off]);
        __syncthreads();
    }
    if (t == 0) a_out[0] = 1.0f / red[0];
}

__global__ void init_x_kernel(float* __restrict__ X, const float* __restrict__ a_p)
{
    const int idx = blockIdx.x * blockDim.x + threadIdx.x;
    const int i = idx >> 8, j = idx & 255;
    X[idx] = (i == j) ? a_p[0] : 0.f;
}

// 256^3 GEMM: mode 0: C = A@B ;  mode 1: C = 2A - A@B  (Newton-Schulz)
__global__ void gemm256_kernel(const float* __restrict__ A, const float* __restrict__ B,
                               float* __restrict__ C, int ns_mode)
{
    __shared__ float As[32][33];
    __shared__ float Bs[32][33];
    const int tx = threadIdx.x, ty = threadIdx.y;
    const int i = blockIdx.y * 32 + ty, j = blockIdx.x * 32 + tx;
    float acc = 0.f;
    for (int kt = 0; kt < Ndim; kt += 32) {
        As[ty][tx] = A[i * Ndim + kt + tx];
        Bs[ty][tx] = B[(kt + ty) * Ndim + j];
        __syncthreads();
#pragma unroll
        for (int mm = 0; mm < 32; mm++)
            acc = fmaf(As[ty][mm], Bs[mm][tx], acc);
        __syncthreads();
    }
    C[i * Ndim + j] = ns_mode ? fmaf(2.f, A[i * Ndim + j], -acc) : acc;
}

// ---------------------------------------------------------------------------
// Persistent ADMM v5: 128 blocks x 2 cols, 256 threads, 8 warps.
// Warp w owns rows [32w, 32w+32). lane = 8q + rp: thread covers rows
// r0=32w+4rp..+3, j-quarter [64q,64q+64): k<JREG registers, rest SMEM.
// w buffer BANK-SKEWED: slot(j) = j + (j>>6) float4s, so the 4 q-group
// addresses of one load land on disjoint banks (1 wavefront, was 4-way
// conflicted in v4). Cross-q reduce via shfl.bfly; ONE barrier per iter.
// Uses Minv symmetry: Tpred[r] = sum_j Minv[j][r] * w[j].
// ---------------------------------------------------------------------------
__global__ void __launch_bounds__(256, 1) admm_kernel(
    const float* __restrict__ Minv, const float* __restrict__ Atb,
    const float* __restrict__ rho_p, const float* __restrict__ lam_p,
    float* __restrict__ out)
{
    extern __shared__ float sm[];
    float*  MinvS = sm;                                // 4*JSMEM rows x 256
    float4* wbuf  = (float4*)(sm + 4 * JSMEM * Ndim);  // [2][WSTRIDE] skewed

    const int tid  = threadIdx.x;
    const int wid  = tid >> 5;
    const int lane = tid & 31;
    const int q    = lane >> 3;
    const int rp   = lane & 7;
    const int r0   = 32 * wid + 4 * rp;
    const int c0   = blockIdx.x * 2;

    const float rho = fabsf(rho_p[0]) + 1e-10f;
    const float tau = fabsf(lam_p[0]) / rho;

    // Stage compact SMEM rows: global j = 64*(cr/JSMEM) + JREG + cr%JSMEM
    {
        const float4* src = (const float4*)Minv;
        float4* dst = (float4*)MinvS;
        for (int idx = tid; idx < 4 * JSMEM * 64; idx += 256) {
            const int cr = idx >> 6, within = idx & 63;
            const int j = 64 * (cr / JSMEM) + JREG + (cr % JSMEM);
            dst[idx] = src[j * 64 + within];
        }
    }

    // Register Minv: j = 64q + k, k < JREG; ull pairs (r0,r1),(r2,r3)
    ull mreg[2 * JREG];
#pragma unroll
    for (int k = 0; k < JREG; k++) {
        const ulonglong2 v =
            __ldg((const ulonglong2*)(Minv + (64 * q + k) * Ndim + r0));
        mreg[2 * k]     = v.x;
        mreg[2 * k + 1] = v.y;
    }

    // Per-thread state for rows r0..r0+3, cols c0,c0+1 (redundant across q)
    float atb[8], u[8], tp[8];
#pragma unroll
    for (int r = 0; r < 4; r++) {
        atb[2 * r]     = __ldg(Atb + (r0 + r) * Kdim + c0);
        atb[2 * r + 1] = __ldg(Atb + (r0 + r) * Kdim + c0 + 1);
        u[2 * r] = 0.f; u[2 * r + 1] = 0.f;
        tp[2 * r] = 0.f; tp[2 * r + 1] = 0.f;
    }
    // init w = Atb, splat-stored at skewed slot; row tid by thread tid
    {
        const float a0 = __ldg(Atb + tid * Kdim + c0);
        const float a1 = __ldg(Atb + tid * Kdim + c0 + 1);
        wbuf[tid + (tid >> 6)] = make_float4(a0, a0, a1, a1);
    }
    __syncthreads();

    const float* MsBase = MinvS + (JSMEM * q) * Ndim + r0;
    const int wslot0 = r0 + (r0 >> 6);   // slot of this thread's first w row

    int b = 0;
    for (int it = 0; it < ITERS; ++it) {
        // quarter q's w slots start at 64q + q = 65q
        const ulonglong2* __restrict__ wb =
            (const ulonglong2*)(wbuf + b * WSTRIDE + 65 * q);

        ull a00 = 0ull, a10 = 0ull, a01 = 0ull, a11 = 0ull;
#pragma unroll
        for (int k = 0; k < JREG; k++) {
            const ulonglong2 wv = wb[k];               // (w0,w0),(w1,w1)
            FMA2(a00, mreg[2 * k],     wv.x, a00);
            FMA2(a10, mreg[2 * k + 1], wv.x, a10);
            FMA2(a01, mreg[2 * k],     wv.y, a01);
            FMA2(a11, mreg[2 * k + 1], wv.y, a11);
        }
#pragma unroll
        for (int k = 0; k < JSMEM; k++) {
            const ulonglong2 m = *(const ulonglong2*)(MsBase + k * Ndim);
            const ulonglong2 wv = wb[JREG + k];
            FMA2(a00, m.x, wv.x, a00);
            FMA2(a10, m.y, wv.x, a10);
            FMA2(a01, m.x, wv.y, a01);
            FMA2(a11, m.y, wv.y, a11);
        }

        // cross-q reduce: bfly xor 8, xor 16 (bit-identical in all lanes)
        ull t0;
        t0 = shfl_xor_u64(a00,  8); ADD2(a00, a00, t0);
        t0 = shfl_xor_u64(a00, 16); ADD2(a00, a00, t0);
        t0 = shfl_xor_u64(a10,  8); ADD2(a10, a10, t0);
        t0 = shfl_xor_u64(a10, 16); ADD2(a10, a10, t0);
        t0 = shfl_xor_u64(a01,  8); ADD2(a01, a01, t0);
        t0 = shfl_xor_u64(a01, 16); ADD2(a01, a01, t0);
        t0 = shfl_xor_u64(a11,  8); ADD2(a11, a11, t0);
        t0 = shfl_xor_u64(a11, 16); ADD2(a11, a11, t0);

        unpack2(tp[0], tp[2], a00);   // col0: r0, r1
        unpack2(tp[4], tp[6], a10);   // col0: r2, r3
        unpack2(tp[1], tp[3], a01);   // col1: r0, r1
        unpack2(tp[5], tp[7], a11);   // col1: r2, r3

        // update (consistent across q); q==0 stores next w
        float w2[8];
#pragma unroll
        for (int i = 0; i < 8; i++) {
            const float g  = tp[i] + u[i];
            float zn = fmaxf(g - tau, 0.f) + fminf(g + tau, 0.f);
            zn = fminf(fmaxf(zn, 0.f), 1.f);
            u[i] += tp[i] - zn;
            w2[i] = fmaf(rho, zn - u[i], atb[i]);
        }
        if (q == 0) {
            float4* wd = wbuf + (b ^ 1) * WSTRIDE + wslot0;
#pragma unroll
            for (int r = 0; r < 4; r++)
                wd[r] = make_float4(w2[2 * r], w2[2 * r],
                                    w2[2 * r + 1], w2[2 * r + 1]);
        }
        __syncthreads();
        b ^= 1;
    }

    if (q == 0) {
#pragma unroll
        for (int r = 0; r < 4; r++)
            *(float2*)(out + (r0 + r) * Kdim + c0) =
                make_float2(tp[2 * r], tp[2 * r + 1]);
    }
}

// ---------------------------------------------------------------------------
extern "C" void kernel_launch(void* const* d_in, const int* in_sizes, int n_in,
                              void* d_out, int out_size)
{
    // metadata order: T, s_A, s_mic_data, rho_param, lam_param
    const float* s_A   = (const float*)d_in[1];
    const float* s_mic = (const float*)d_in[2];
    const float* rho_p = (const float*)d_in[3];
    const float* lam_p = (const float*)d_in[4];
    float* out = (float*)d_out;

    float *G, *Atb, *X0, *X1, *Y, *ap;
    cudaGetSymbolAddress((void**)&G,   g_G);
    cudaGetSymbolAddress((void**)&Atb, g_Atb);
    cudaGetSymbolAddress((void**)&X0,  g_X0);
    cudaGetSymbolAddress((void**)&X1,  g_X1);
    cudaGetSymbolAddress((void**)&Y,   g_Y);
    cudaGetSymbolAddress((void**)&ap,  g_a);

    const size_t shmem = (size_t)(4 * JSMEM * Ndim) * sizeof(float)
                       + 2 * WSTRIDE * sizeof(float4);
    cudaFuncSetAttribute(admm_kernel, cudaFuncAttributeMaxDynamicSharedMemorySize,
                         (int)shmem);

    // atomic-combined A^T X with 4-way M split (buffers zeroed first)
    cudaMemsetAsync(G,   0, Ndim * Ndim * sizeof(float));
    cudaMemsetAsync(Atb, 0, Ndim * Kdim * sizeof(float));
    dim3 tb(32, 32);
    dim3 gbz(8, 8, 4);
    atx_kernel<<<gbz, tb>>>(s_A, s_A,   G,   rho_p, 1);
    atx_kernel<<<gbz, tb>>>(s_A, s_mic, Atb, rho_p, 0);

    // Newton-Schulz inverse: X0 = I/||G||inf; X <- 2X - X@(G@X)
    norm_kernel<<<1, 256>>>(G, ap);
    init_x_kernel<<<256, 256>>>(X0, ap);
    dim3 gb(8, 8);
    float* Xc = X0; float* Xn = X1;
    for (int i = 0; i < NS_ITERS; i++) {
        gemm256_kernel<<<gb, tb>>>(G,  Xc, Y,  0);  // Y  = G@X
        gemm256_kernel<<<gb, tb>>>(Xc, Y,  Xn, 1);  // Xn = 2X - X@Y
        float* t = Xc; Xc = Xn; Xn = t;
    }
    // NS_ITERS even -> result back in X0 (== Xc)

    admm_kernel<<<128, 256, shmem>>>(Xc, Atb, rho_p, lam_p, out);
}